// round 9
// baseline (speedup 1.0000x reference)
#include <cuda_runtime.h>

// ---------------------------------------------------------------------------
// DeformAttnwMotion, round 8: occupancy push.
//   R7 -> R8:
//   1. 512 threads/block: (16 px, 16 cgrp, 2 head-groups). Per-thread state
//      halves (4 heads x 8 c) -> ~120 regs -> 16 warps/SM (occ 12.5->25%).
//   2. No weight smem: all weight reads are warp-uniform LDG from g_WT
//      (L2-resident broadcast). smem 165KB -> ~99KB.
//   3. agg staging padded (stride 130) -> conflict-free STS.64/LDS.64.
// Math identical to R7:
//   logit_s = (Wk_h^T qp_h) . kv_s   (s-const terms drop out of softmax)
//   out_h   = Wv_h . (sum_s w_s kv_s)/Z + bv
//
// d_out layout (float32):
//   [0 , 2097152)            out      : (4,128,64,64)
//   [2097152 , 3276800)      kv0_attn : (32, 9, 4096)
//   [3276800 , 4456448)      kv1_attn : (32, 9, 4096)
// ---------------------------------------------------------------------------

typedef unsigned long long ull;

#define BB   4
#define CC   128
#define DD   4096
#define SS   18
#define OCH  128
#define NHD  8
#define TPX  16
#define NT   512
#define SCALE_F 0.25f

// Transposed weights scratch: [m][c][oc], m = 0:Wq 1:Wk 2:Wv
__device__ float g_WT[3 * CC * OCH];

__global__ void transpose_w_kernel(const float* __restrict__ Wq,
                                   const float* __restrict__ Wk,
                                   const float* __restrict__ Wv) {
    int idx = blockIdx.x * blockDim.x + threadIdx.x;
    if (idx >= 3 * CC * OCH) return;
    int m   = idx >> 14;
    int rem = idx & 16383;
    int r   = rem >> 7;     // oc
    int c   = rem & 127;    // c
    const float* W = (m == 0) ? Wq : (m == 1) ? Wk : Wv;
    g_WT[m * 16384 + c * OCH + r] = W[r * CC + c];
}

// ---------------- packed f32x2 helpers ----------------
__device__ __forceinline__ ull pack2(float lo, float hi) {
    ull r; asm("mov.b64 %0, {%1, %2};" : "=l"(r) : "f"(lo), "f"(hi)); return r;
}
__device__ __forceinline__ float2 unpack2(ull v) {
    float2 r; asm("mov.b64 {%0, %1}, %2;" : "=f"(r.x), "=f"(r.y) : "l"(v)); return r;
}
__device__ __forceinline__ ull fma2(ull a, ull b, ull c) {
    ull d; asm("fma.rn.f32x2 %0, %1, %2, %3;" : "=l"(d) : "l"(a), "l"(b), "l"(c)); return d;
}
__device__ __forceinline__ void cp16(float* dst, const float* src) {
    unsigned sa = (unsigned)__cvta_generic_to_shared(dst);
    asm volatile("cp.async.cg.shared.global [%0], [%1], 16;" :: "r"(sa), "l"(src));
}
#define CP_COMMIT() asm volatile("cp.async.commit_group;" ::: "memory")
#define CP_WAIT(n)  asm volatile("cp.async.wait_group %0;" :: "n"(n) : "memory")

// smem float offsets
#define SM_QP   0          // 2048 : qp[oc][px] (P1) / logit partials [h][cg][px]
#define SM_LOG  2048       // 2304 : logits [h][s][px]
#define SM_WGT  4352       // 128  : w[h][px], later invZ[h][px]
#define SM_KV   4480       // 4096 : kv double buffer [2][c][px]
#define SM_AGG  8576       // 16640: agg [h][px][c] padded, stride 130
#define AGGSTR  130
#define AGH     (TPX * AGGSTR)      // 2080
#define SM_TOTAL_F (8576 + NHD * AGH)   // 25216 floats = 100864 B

__global__ void __launch_bounds__(NT, 1)
deform_attn_kernel(const float* __restrict__ q,
                   const float* __restrict__ kv,
                   const float* __restrict__ bq,
                   const float* __restrict__ bk,   // unused (softmax shift-inv)
                   const float* __restrict__ bv,
                   float* __restrict__ out) {
    extern __shared__ float sm[];

    const int t   = threadIdx.x;       // 512
    const int px  = t & 15;            // pixel in tile
    const int cg  = (t >> 4) & 15;     // c-group 0..15 (8 channels)
    const int c0  = cg * 8;
    const int hg  = t >> 8;            // head-group 0..1
    const int h0  = hg * 4;
    const int b   = blockIdx.y;
    const int pxg = blockIdx.x * TPX;

    float* attn0 = out + (size_t)BB * OCH * DD;
    float* attn1 = attn0 + (size_t)BB * NHD * 9 * DD;

    const int ldc  = t >> 2;           // 0..127 : channel for cp.async
    const int lds4 = (t & 3) * 4;      // 4-px segment

    // ---- P0: q tile -> buf0 (A), kv s=0 -> buf1 (B) -------------------------
    cp16(sm + SM_KV + ldc * 16 + lds4,
         q + ((size_t)(b * CC + ldc)) * DD + pxg + lds4);
    CP_COMMIT();   // A
    cp16(sm + SM_KV + 2048 + ldc * 16 + lds4,
         kv + (((size_t)(b * CC + ldc)) * SS + 0) * DD + pxg + lds4);
    CP_COMMIT();   // B
    CP_WAIT(1);    // A done
    __syncthreads();

    // ---- P1: qp[oc][px], thread = (og = t>>4, px): 4 oc each ---------------
    {
        const int og   = t >> 4;           // 0..31
        const int oc0p = og * 4;
        ull acc0 = pack2(bq[oc0p],     bq[oc0p + 1]);
        ull acc1 = pack2(bq[oc0p + 2], bq[oc0p + 3]);
        const float* wbase = g_WT + oc0p;  // WqT
#pragma unroll 4
        for (int c = 0; c < CC; ++c) {
            float qv = sm[SM_KV + c * 16 + px];
            ull q2 = pack2(qv, qv);
            ulonglong2 w = *reinterpret_cast<const ulonglong2*>(wbase + c * OCH);
            acc0 = fma2(w.x, q2, acc0);
            acc1 = fma2(w.y, q2, acc1);
        }
        float2 v0 = unpack2(acc0), v1 = unpack2(acc1);
        sm[SM_QP + (oc0p)     * 16 + px] = v0.x;
        sm[SM_QP + (oc0p + 1) * 16 + px] = v0.y;
        sm[SM_QP + (oc0p + 2) * 16 + px] = v1.x;
        sm[SM_QP + (oc0p + 3) * 16 + px] = v1.y;
    }
    __syncthreads();

    // ---- P2: qtilde[h0..h0+3][c0..c0+7] in registers ------------------------
    ull qt2[4][4];
#pragma unroll
    for (int h = 0; h < 4; ++h) {
        const int hh = h0 + h;
        ull qp2[8];
#pragma unroll
        for (int j = 0; j < 8; ++j)
            qp2[j] = pack2(sm[SM_QP + (hh * 16 + 2 * j) * 16 + px],
                           sm[SM_QP + (hh * 16 + 2 * j + 1) * 16 + px]);
        float qts[8];
#pragma unroll
        for (int i = 0; i < 8; ++i) {
            const ull* wr = reinterpret_cast<const ull*>(
                g_WT + 16384 + (c0 + i) * OCH + hh * 16);   // WkT
            ull a = 0ull;
#pragma unroll
            for (int j = 0; j < 8; ++j) a = fma2(wr[j], qp2[j], a);
            float2 v = unpack2(a);
            qts[i] = v.x + v.y;
        }
#pragma unroll
        for (int u = 0; u < 4; ++u)
            qt2[h][u] = pack2(qts[2 * u], qts[2 * u + 1]);
    }

    // ---- sample loop ---------------------------------------------------------
    ull agg2[4][4];
#pragma unroll
    for (int h = 0; h < 4; ++h)
#pragma unroll
        for (int u = 0; u < 4; ++u) agg2[h][u] = 0ull;

    float Zf = 0.f, Z0 = 0.f, Z1 = 0.f;      // live in t<128 threads
    const int rh = t >> 4;                    // reducer head (t<128)
    const int rp = t & 15;                    // reducer pixel

    for (int s = 0; s < SS; ++s) {
        if (s < SS - 1) {
            cp16(sm + SM_KV + (s & 1) * 2048 + ldc * 16 + lds4,
                 kv + (((size_t)(b * CC + ldc)) * SS + (s + 1)) * DD + pxg + lds4);
            CP_COMMIT();
            CP_WAIT(1);
        } else {
            CP_WAIT(0);
        }
        __syncthreads();

        const float* cur = sm + SM_KV + ((s + 1) & 1) * 2048;
        ull kv2[4];
#pragma unroll
        for (int u = 0; u < 4; ++u)
            kv2[u] = pack2(cur[(c0 + 2 * u) * 16 + px],
                           cur[(c0 + 2 * u + 1) * 16 + px]);

        // partial logits for 4 heads -> smem
#pragma unroll
        for (int h = 0; h < 4; ++h) {
            ull a = 0ull;
#pragma unroll
            for (int u = 0; u < 4; ++u) a = fma2(qt2[h][u], kv2[u], a);
            float2 v = unpack2(a);
            sm[SM_QP + (h0 + h) * 256 + cg * 16 + px] = v.x + v.y;
        }
        __syncthreads();

        // reduce 16 partials, exp, weight
        if (t < 128) {
            float sum = 0.f;
#pragma unroll
            for (int j = 0; j < 16; ++j)
                sum += sm[SM_QP + rh * 256 + j * 16 + rp];
            float lg = sum * SCALE_F;
            sm[SM_LOG + rh * (SS * 16) + s * 16 + rp] = lg;
            float w = __expf(lg);
            sm[SM_WGT + rh * 16 + rp] = w;
            Zf += w;
            if (s < 9) Z0 += w; else Z1 += w;
        }
        __syncthreads();

        // agg[h] += w[h] * kv
#pragma unroll
        for (int h = 0; h < 4; ++h) {
            float w = sm[SM_WGT + (h0 + h) * 16 + px];
            ull w2 = pack2(w, w);
#pragma unroll
            for (int u = 0; u < 4; ++u)
                agg2[h][u] = fma2(kv2[u], w2, agg2[h][u]);
        }
    }
    __syncthreads();   // all w reads done before invZ overwrite

    // ---- stage agg -> smem, invZ -> SM_WGT -----------------------------------
    if (t < 128) sm[SM_WGT + rh * 16 + rp] = 1.f / Zf;
#pragma unroll
    for (int h = 0; h < 4; ++h) {
        float2* dst = reinterpret_cast<float2*>(
            sm + SM_AGG + (h0 + h) * AGH + px * AGGSTR + c0);
#pragma unroll
        for (int u = 0; u < 4; ++u) dst[u] = unpack2(agg2[h][u]);
    }
    __syncthreads();

    // ---- P5: out[oc][px] = (WvT . agg_h) * invZ + bv -------------------------
    {
        const int og   = t >> 4;          // 0..31
        const int oc0p = og * 4;
        const int h5   = og >> 2;         // head = oc0p/16
        ull acc0 = 0ull, acc1 = 0ull;
        const float* aggp  = sm + SM_AGG + h5 * AGH + px * AGGSTR;
        const float* wbase = g_WT + 32768 + oc0p;   // WvT
#pragma unroll 4
        for (int c = 0; c < CC; c += 2) {
            float2 a = *reinterpret_cast<const float2*>(aggp + c);
            ull a0 = pack2(a.x, a.x);
            ull a1 = pack2(a.y, a.y);
            ulonglong2 w0 = *reinterpret_cast<const ulonglong2*>(wbase + c * OCH);
            ulonglong2 w1 = *reinterpret_cast<const ulonglong2*>(wbase + (c + 1) * OCH);
            acc0 = fma2(w0.x, a0, acc0);
            acc1 = fma2(w0.y, a0, acc1);
            acc0 = fma2(w1.x, a1, acc0);
            acc1 = fma2(w1.y, a1, acc1);
        }
        float iz = sm[SM_WGT + h5 * 16 + px];
        float2 v0 = unpack2(acc0), v1 = unpack2(acc1);
        size_t base = ((size_t)(b * OCH + oc0p)) * DD + pxg + px;
        out[base]          = v0.x * iz + bv[oc0p];
        out[base + DD]     = v0.y * iz + bv[oc0p + 1];
        out[base + 2 * DD] = v1.x * iz + bv[oc0p + 2];
        out[base + 3 * DD] = v1.y * iz + bv[oc0p + 3];
    }

    // ---- epilogue: half softmaxes from smem logits ---------------------------
    if (t < 128) {
        float iz0 = 1.f / Z0, iz1 = 1.f / Z1;
        size_t base = ((size_t)(b * NHD + rh) * 9) * DD + pxg + rp;
#pragma unroll
        for (int s = 0; s < 9; ++s) {
            attn0[base + (size_t)s * DD] =
                __expf(sm[SM_LOG + rh * (SS * 16) + s * 16 + rp]) * iz0;
            attn1[base + (size_t)s * DD] =
                __expf(sm[SM_LOG + rh * (SS * 16) + (s + 9) * 16 + rp]) * iz1;
        }
    }
}

// ---------------------------------------------------------------------------
extern "C" void kernel_launch(void* const* d_in, const int* in_sizes, int n_in,
                              void* d_out, int out_size) {
    const float* q  = (const float*)d_in[0];
    const float* kv = (const float*)d_in[1];
    const float* Wq = (const float*)d_in[2];
    const float* bq = (const float*)d_in[3];
    const float* Wk = (const float*)d_in[4];
    const float* bk = (const float*)d_in[5];
    const float* Wv = (const float*)d_in[6];
    const float* bv = (const float*)d_in[7];
    float* out = (float*)d_out;

    cudaFuncSetAttribute(deform_attn_kernel,
                         cudaFuncAttributeMaxDynamicSharedMemorySize,
                         SM_TOTAL_F * 4);

    transpose_w_kernel<<<192, 256>>>(Wq, Wk, Wv);
    deform_attn_kernel<<<dim3(DD / TPX, BB), NT, SM_TOTAL_F * 4>>>(
        q, kv, bq, bk, bv, out);
}

// round 10
// speedup vs baseline: 1.5626x; 1.5626x over previous
#include <cuda_runtime.h>

// ---------------------------------------------------------------------------
// DeformAttnwMotion, round 9: barrier + LSU reduction on the R7 base.
//   R7 -> R9:
//   1. Sample loop processes PAIRS (9 iters): 2 barriers per pair instead of
//      3 per sample (58 -> ~24 BARs per tile). kv ring = 3 pairs (6 slots),
//      prefetch distance 2, cp wait folded into the post-reduce barrier.
//   2. qp staged transposed [px][oc] (pad 130): P2 qp reads become LDS.64;
//      P1/P2/P5 weight reads are LDS.128 broadcast.
//   3. Store w=exp(logit) once; epilogue reuses it (no 2nd expf).
// Math identical:
//   logit_s = (Wk_h^T qp_h) . kv_s ; out_h = Wv_h.(sum w_s kv_s)/Z + bv
//
// d_out layout (float32):
//   [0 , 2097152)            out      : (4,128,64,64)
//   [2097152 , 3276800)      kv0_attn : (32, 9, 4096)
//   [3276800 , 4456448)      kv1_attn : (32, 9, 4096)
// ---------------------------------------------------------------------------

typedef unsigned long long ull;

#define BB   4
#define CC   128
#define DD   4096
#define SS   18
#define OCH  128
#define NHD  8
#define TPX  16
#define NT   256
#define NP   9
#define SCALE_F 0.25f

// Transposed weights scratch: [m][c][oc], m = 0:Wq 1:Wk 2:Wv
__device__ float g_WT[3 * CC * OCH];

__global__ void transpose_w_kernel(const float* __restrict__ Wq,
                                   const float* __restrict__ Wk,
                                   const float* __restrict__ Wv) {
    int idx = blockIdx.x * blockDim.x + threadIdx.x;
    if (idx >= 3 * CC * OCH) return;
    int m   = idx >> 14;
    int rem = idx & 16383;
    int r   = rem >> 7;     // oc
    int c   = rem & 127;    // c
    const float* W = (m == 0) ? Wq : (m == 1) ? Wk : Wv;
    g_WT[m * 16384 + c * OCH + r] = W[r * CC + c];
}

// ---------------- packed f32x2 helpers ----------------
__device__ __forceinline__ ull pack2(float lo, float hi) {
    ull r; asm("mov.b64 %0, {%1, %2};" : "=l"(r) : "f"(lo), "f"(hi)); return r;
}
__device__ __forceinline__ float2 unpack2(ull v) {
    float2 r; asm("mov.b64 {%0, %1}, %2;" : "=f"(r.x), "=f"(r.y) : "l"(v)); return r;
}
__device__ __forceinline__ ull fma2(ull a, ull b, ull c) {
    ull d; asm("fma.rn.f32x2 %0, %1, %2, %3;" : "=l"(d) : "l"(a), "l"(b), "l"(c)); return d;
}
__device__ __forceinline__ void cp16(float* dst, const float* src) {
    unsigned sa = (unsigned)__cvta_generic_to_shared(dst);
    asm volatile("cp.async.cg.shared.global [%0], [%1], 16;" :: "r"(sa), "l"(src));
}
#define CP_COMMIT() asm volatile("cp.async.commit_group;" ::: "memory")
#define CP_WAIT(n)  asm volatile("cp.async.wait_group %0;" :: "n"(n) : "memory")

// smem float offsets
#define SM_WA   0          // 16384 : Wq^T, later Wv^T
#define SM_WK   16384      // 16640 : Wk^T, later agg [h][px][130]
#define SM_AGG  16384
#define SM_QP   33024      // 2080  : qp [px][130]
#define SM_PART 35104      // 4096  : partials [2][h][cg][px]
#define SM_W8   39200      // 256   : w [2][h][px], later invZ [h][px]
#define SM_LOGW 39456      // 2304  : w values [h][18][px]
#define SM_KV   41760      // 12288 : kv ring, 6 slots of [c][16px]
#define SM_TOTAL_F 54048   // 216192 bytes

#define LOAD_PAIR(p_, slot_) do {                                            \
    _Pragma("unroll")                                                        \
    for (int k_ = 0; k_ < 4; ++k_) {                                         \
        int i_ = t + k_ * 256;                                               \
        int smp_ = i_ >> 9;                                                  \
        int c_   = (i_ >> 2) & 127;                                          \
        int sg_  = i_ & 3;                                                   \
        cp16(sm + SM_KV + ((slot_) + smp_) * 2048 + c_ * 16 + sg_ * 4,       \
             kv + (((size_t)(b * CC + c_)) * SS + (2 * (p_) + smp_)) * DD    \
                + pxg + sg_ * 4);                                            \
    } } while (0)

__global__ void __launch_bounds__(NT, 1)
deform_attn_kernel(const float* __restrict__ q,
                   const float* __restrict__ kv,
                   const float* __restrict__ bq,
                   const float* __restrict__ bk,   // unused (softmax shift-inv)
                   const float* __restrict__ bv,
                   float* __restrict__ out) {
    extern __shared__ float sm[];

    const int t   = threadIdx.x;     // 256
    const int px  = t & 15;          // pixel in tile
    const int cg  = t >> 4;          // c-group 0..15 (8 channels) / oc-group
    const int c0  = cg * 8;
    const int b   = blockIdx.y;
    const int pxg = blockIdx.x * TPX;

    float* attn0 = out + (size_t)BB * OCH * DD;
    float* attn1 = attn0 + (size_t)BB * NHD * 9 * DD;

    // ---- G0: WqT, WkT, q tile (into kv slots 4,5 region) --------------------
#pragma unroll
    for (int k = 0; k < 16; ++k) {
        int i = t + k * 256;
        cp16(sm + SM_WA + i * 4, g_WT + i * 4);
    }
#pragma unroll
    for (int k = 0; k < 16; ++k) {
        int i = t + k * 256;
        cp16(sm + SM_WK + i * 4, g_WT + 16384 + i * 4);
    }
#pragma unroll
    for (int k = 0; k < 2; ++k) {
        int i = t + k * 256;
        int c = i >> 2, sg = i & 3;
        cp16(sm + SM_KV + 4 * 2048 + c * 16 + sg * 4,
             q + ((size_t)(b * CC + c)) * DD + pxg + sg * 4);
    }
    CP_COMMIT();                       // G0
    LOAD_PAIR(0, 0); CP_COMMIT();      // G1: pair0 -> slots 0,1
    LOAD_PAIR(1, 2); CP_COMMIT();      // G2: pair1 -> slots 2,3
    CP_WAIT(2);                        // G0 done
    __syncthreads();

    // ---- P1: qp = Wq.x + bq -> sm[SM_QP + px*130 + oc] ----------------------
    {
        const int oc0 = cg * 8;
        ull a0 = pack2(bq[oc0],     bq[oc0 + 1]);
        ull a1 = pack2(bq[oc0 + 2], bq[oc0 + 3]);
        ull a2 = pack2(bq[oc0 + 4], bq[oc0 + 5]);
        ull a3 = pack2(bq[oc0 + 6], bq[oc0 + 7]);
        const float* qt_ = sm + SM_KV + 4 * 2048;
#pragma unroll 4
        for (int c = 0; c < CC; ++c) {
            float qv = qt_[c * 16 + px];
            ull q2 = pack2(qv, qv);
            const ulonglong2* w =
                reinterpret_cast<const ulonglong2*>(sm + SM_WA + c * OCH + oc0);
            ulonglong2 w0 = w[0], w1 = w[1];
            a0 = fma2(w0.x, q2, a0);
            a1 = fma2(w0.y, q2, a1);
            a2 = fma2(w1.x, q2, a2);
            a3 = fma2(w1.y, q2, a3);
        }
        float2* qp = reinterpret_cast<float2*>(sm + SM_QP + px * 130 + oc0);
        qp[0] = unpack2(a0); qp[1] = unpack2(a1);
        qp[2] = unpack2(a2); qp[3] = unpack2(a3);
    }
    __syncthreads();   // qp published; WqT free

    // G3: WvT -> SM_WA (overwrites WqT)
#pragma unroll
    for (int k = 0; k < 16; ++k) {
        int i = t + k * 256;
        cp16(sm + SM_WA + i * 4, g_WT + 32768 + i * 4);
    }
    CP_COMMIT();

    // ---- P2: qtilde[h][c0..c0+7] in registers -------------------------------
    ull qt2[NHD][4];
#pragma unroll
    for (int h = 0; h < NHD; ++h) {
        const ull* qpp =
            reinterpret_cast<const ull*>(sm + SM_QP + px * 130 + h * 16);
        ull qp2[8];
#pragma unroll
        for (int j = 0; j < 8; ++j) qp2[j] = qpp[j];
        float qts[8];
#pragma unroll
        for (int i = 0; i < 8; ++i) {
            const ulonglong2* wr = reinterpret_cast<const ulonglong2*>(
                sm + SM_WK + (c0 + i) * OCH + h * 16);
            ulonglong2 wa = wr[0], wb = wr[1], wc = wr[2], wd = wr[3];
            ull a = 0ull;
            a = fma2(wa.x, qp2[0], a); a = fma2(wa.y, qp2[1], a);
            a = fma2(wb.x, qp2[2], a); a = fma2(wb.y, qp2[3], a);
            a = fma2(wc.x, qp2[4], a); a = fma2(wc.y, qp2[5], a);
            a = fma2(wd.x, qp2[6], a); a = fma2(wd.y, qp2[7], a);
            float2 v = unpack2(a);
            qts[i] = v.x + v.y;
        }
#pragma unroll
        for (int u = 0; u < 4; ++u)
            qt2[h][u] = pack2(qts[2 * u], qts[2 * u + 1]);
    }
    CP_WAIT(2);        // G1 (pair0) done; G2,G3 may pend
    __syncthreads();

    // ---- pair loop -----------------------------------------------------------
    ull agg2[NHD][4];
#pragma unroll
    for (int h = 0; h < NHD; ++h)
#pragma unroll
        for (int u = 0; u < 4; ++u) agg2[h][u] = 0ull;

    float Zf = 0.f, Z0 = 0.f, Z1 = 0.f;      // reducers (t<128) only
    const int rh = t >> 4;
    const int rp = t & 15;

    for (int p = 0; p < NP; ++p) {
        const int slot0 = (p % 3) * 2;
        const float* cu0 = sm + SM_KV + slot0 * 2048;
        const float* cu1 = cu0 + 2048;

        ull kva[4], kvb[4];
#pragma unroll
        for (int u = 0; u < 4; ++u) {
            kva[u] = pack2(cu0[(c0 + 2 * u) * 16 + px],
                           cu0[(c0 + 2 * u + 1) * 16 + px]);
            kvb[u] = pack2(cu1[(c0 + 2 * u) * 16 + px],
                           cu1[(c0 + 2 * u + 1) * 16 + px]);
        }

        // partial logits (both samples) -> smem
#pragma unroll
        for (int h = 0; h < NHD; ++h) {
            ull a = 0ull, bb = 0ull;
#pragma unroll
            for (int u = 0; u < 4; ++u) {
                a  = fma2(qt2[h][u], kva[u], a);
                bb = fma2(qt2[h][u], kvb[u], bb);
            }
            float2 va = unpack2(a), vb = unpack2(bb);
            sm[SM_PART + h * 256 + cg * 16 + px]        = va.x + va.y;
            sm[SM_PART + 2048 + h * 256 + cg * 16 + px] = vb.x + vb.y;
        }
        __syncthreads();   // BAR1: partials visible

        if (t < 128) {
#pragma unroll
            for (int smp = 0; smp < 2; ++smp) {
                const float* pp = sm + SM_PART + smp * 2048 + rh * 256 + rp;
                float sum = 0.f;
#pragma unroll
                for (int j = 0; j < 16; ++j) sum += pp[j * 16];
                float w = __expf(sum * SCALE_F);
                int s = 2 * p + smp;
                sm[SM_W8 + smp * 128 + rh * 16 + rp] = w;
                sm[SM_LOGW + rh * 288 + s * 16 + rp] = w;
                Zf += w;
                if (s < 9) Z0 += w; else Z1 += w;
            }
        }

        if (p + 2 < NP) {
            LOAD_PAIR(p + 2, ((p + 2) % 3) * 2);
            CP_COMMIT();
            CP_WAIT(1);    // pair(p+1) done
        } else {
            CP_WAIT(0);
        }
        __syncthreads();   // BAR2: w visible + kv(p+1) visible

        // agg += w0*kv0 + w1*kv1
#pragma unroll
        for (int h = 0; h < NHD; ++h) {
            float wa = sm[SM_W8 + h * 16 + px];
            float wb = sm[SM_W8 + 128 + h * 16 + px];
            ull wa2 = pack2(wa, wa), wb2 = pack2(wb, wb);
#pragma unroll
            for (int u = 0; u < 4; ++u) {
                agg2[h][u] = fma2(kva[u], wa2, agg2[h][u]);
                agg2[h][u] = fma2(kvb[u], wb2, agg2[h][u]);
            }
        }
    }
    __syncthreads();   // last w reads done

    // ---- stage agg -> SM_AGG (stride 130), invZ -> SM_W8 ---------------------
    if (t < 128) sm[SM_W8 + rh * 16 + rp] = 1.f / Zf;
#pragma unroll
    for (int h = 0; h < NHD; ++h) {
        float2* dst = reinterpret_cast<float2*>(
            sm + SM_AGG + h * 2080 + px * 130 + c0);
#pragma unroll
        for (int u = 0; u < 4; ++u) dst[u] = unpack2(agg2[h][u]);
    }
    __syncthreads();

    // ---- P5: out[oc][px] = (WvT . agg_h) * invZ + bv -------------------------
    {
        const int oc0 = cg * 8;
        const int h5  = cg >> 1;
        const float* ag = sm + SM_AGG + h5 * 2080 + px * 130;
        ull a0 = 0ull, a1 = 0ull, a2 = 0ull, a3 = 0ull;
#pragma unroll 4
        for (int c = 0; c < CC; c += 2) {
            float2 av = *reinterpret_cast<const float2*>(ag + c);
            ull p0 = pack2(av.x, av.x);
            ull p1 = pack2(av.y, av.y);
            const ulonglong2* w0 =
                reinterpret_cast<const ulonglong2*>(sm + SM_WA + c * OCH + oc0);
            const ulonglong2* w1 =
                reinterpret_cast<const ulonglong2*>(sm + SM_WA + (c + 1) * OCH + oc0);
            ulonglong2 wA = w0[0], wB = w0[1], wC = w1[0], wD = w1[1];
            a0 = fma2(wA.x, p0, a0); a1 = fma2(wA.y, p0, a1);
            a2 = fma2(wB.x, p0, a2); a3 = fma2(wB.y, p0, a3);
            a0 = fma2(wC.x, p1, a0); a1 = fma2(wC.y, p1, a1);
            a2 = fma2(wD.x, p1, a2); a3 = fma2(wD.y, p1, a3);
        }
        float iz = sm[SM_W8 + h5 * 16 + px];
        float2 v0 = unpack2(a0), v1 = unpack2(a1);
        float2 v2 = unpack2(a2), v3 = unpack2(a3);
        size_t base = ((size_t)(b * OCH + oc0)) * DD + pxg + px;
        out[base]          = v0.x * iz + bv[oc0];
        out[base + DD]     = v0.y * iz + bv[oc0 + 1];
        out[base + 2 * DD] = v1.x * iz + bv[oc0 + 2];
        out[base + 3 * DD] = v1.y * iz + bv[oc0 + 3];
        out[base + 4 * DD] = v2.x * iz + bv[oc0 + 4];
        out[base + 5 * DD] = v2.y * iz + bv[oc0 + 5];
        out[base + 6 * DD] = v3.x * iz + bv[oc0 + 6];
        out[base + 7 * DD] = v3.y * iz + bv[oc0 + 7];
    }

    // ---- epilogue: half softmaxes from stored w ------------------------------
    if (t < 128) {
        float iz0 = 1.f / Z0, iz1 = 1.f / Z1;
        size_t base = ((size_t)(b * NHD + rh) * 9) * DD + pxg + rp;
#pragma unroll
        for (int s = 0; s < 9; ++s) {
            attn0[base + (size_t)s * DD] =
                sm[SM_LOGW + rh * 288 + s * 16 + rp] * iz0;
            attn1[base + (size_t)s * DD] =
                sm[SM_LOGW + rh * 288 + (s + 9) * 16 + rp] * iz1;
        }
    }
}

// ---------------------------------------------------------------------------
extern "C" void kernel_launch(void* const* d_in, const int* in_sizes, int n_in,
                              void* d_out, int out_size) {
    const float* q  = (const float*)d_in[0];
    const float* kv = (const float*)d_in[1];
    const float* Wq = (const float*)d_in[2];
    const float* bq = (const float*)d_in[3];
    const float* Wk = (const float*)d_in[4];
    const float* bk = (const float*)d_in[5];
    const float* Wv = (const float*)d_in[6];
    const float* bv = (const float*)d_in[7];
    float* out = (float*)d_out;

    cudaFuncSetAttribute(deform_attn_kernel,
                         cudaFuncAttributeMaxDynamicSharedMemorySize,
                         SM_TOTAL_F * 4);

    transpose_w_kernel<<<192, 256>>>(Wq, Wk, Wv);
    deform_attn_kernel<<<dim3(DD / TPX, BB), NT, SM_TOTAL_F * 4>>>(
        q, kv, bq, bk, bv, out);
}

// round 11
// speedup vs baseline: 1.6576x; 1.0608x over previous
#include <cuda_runtime.h>

// ---------------------------------------------------------------------------
// DeformAttnwMotion, round 10: conflict-free smem + 1-barrier pipelined loop.
//   R9 -> R10:
//   1. Interleaved channel ownership (thread channels c = cg+16k): kv LDS
//      conflict-free (was 2-way). Partial rows padded to 272 (=16 mod 32):
//      reducer loads conflict-free (was 2-way).
//   2. Full-block reducer: 256 threads = (sample-of-pair, head, px); per-
//      thread partial Z merged once at end. No idle warps in reduce.
//   3. Software-pipelined sample loop, ONE barrier per pair:
//      segment(i): reduce(i) || agg(i-1) || load kreg(i+1) || partials(i+1).
//      Two kv register generations (parity). w double-buffering via distinct
//      LOGW sample slots.
// Math identical:
//   logit_s = (Wk_h^T qp_h) . kv_s ; out_h = Wv_h.(sum w_s kv_s)/Z + bv
//
// d_out layout (float32):
//   [0 , 2097152)            out      : (4,128,64,64)
//   [2097152 , 3276800)      kv0_attn : (32, 9, 4096)
//   [3276800 , 4456448)      kv1_attn : (32, 9, 4096)
// ---------------------------------------------------------------------------

typedef unsigned long long ull;

#define BB   4
#define CC   128
#define DD   4096
#define SS   18
#define OCH  128
#define NHD  8
#define TPX  16
#define NT   256
#define NP   9
#define SCALE_F 0.25f

__device__ float g_WT[3 * CC * OCH];

__global__ void transpose_w_kernel(const float* __restrict__ Wq,
                                   const float* __restrict__ Wk,
                                   const float* __restrict__ Wv) {
    int idx = blockIdx.x * blockDim.x + threadIdx.x;
    if (idx >= 3 * CC * OCH) return;
    int m   = idx >> 14;
    int rem = idx & 16383;
    int r   = rem >> 7;
    int c   = rem & 127;
    const float* W = (m == 0) ? Wq : (m == 1) ? Wk : Wv;
    g_WT[m * 16384 + c * OCH + r] = W[r * CC + c];
}

__device__ __forceinline__ ull pack2(float lo, float hi) {
    ull r; asm("mov.b64 %0, {%1, %2};" : "=l"(r) : "f"(lo), "f"(hi)); return r;
}
__device__ __forceinline__ float2 unpack2(ull v) {
    float2 r; asm("mov.b64 {%0, %1}, %2;" : "=f"(r.x), "=f"(r.y) : "l"(v)); return r;
}
__device__ __forceinline__ ull fma2(ull a, ull b, ull c) {
    ull d; asm("fma.rn.f32x2 %0, %1, %2, %3;" : "=l"(d) : "l"(a), "l"(b), "l"(c)); return d;
}
__device__ __forceinline__ void cp16(float* dst, const float* src) {
    unsigned sa = (unsigned)__cvta_generic_to_shared(dst);
    asm volatile("cp.async.cg.shared.global [%0], [%1], 16;" :: "r"(sa), "l"(src));
}
#define CP_COMMIT() asm volatile("cp.async.commit_group;" ::: "memory")
#define CP_WAIT(n)  asm volatile("cp.async.wait_group %0;" :: "n"(n) : "memory")

// smem float offsets (total 56448 floats = 225792 B)
#define SM_WA    0        // 16384 : WqT, then WvT
#define SM_WK    16384    // WkT (16384); epilogue: AGG [h][px][130] (16640)
#define SM_AGG   16384
#define SM_PART  33024    // 8704 : pbuf[2][smp][h][272]
#define SM_QP    33024    // alias (prologue only): qp [px][130]
#define SM_Z     33024    // alias (post-loop): z parts [2][256]
#define SM_IZ    33536    // alias : invZ [h][px] (128)
#define SM_LOGW  41728    // 2432 : w [h][304]  (18 samples * 16 px, pad 304)
#define SM_KV    44160    // 12288 : kv ring, 6 slots of [c][16]
#define SM_TOTAL_F 56448

#define LOAD_PAIR(p_, slot_) do {                                            \
    _Pragma("unroll")                                                        \
    for (int k_ = 0; k_ < 4; ++k_) {                                         \
        int i_ = t + k_ * 256;                                               \
        int smp_ = i_ >> 9;                                                  \
        int c_   = (i_ >> 2) & 127;                                          \
        int sg_  = i_ & 3;                                                   \
        cp16(sm + SM_KV + ((slot_) + smp_) * 2048 + c_ * 16 + sg_ * 4,       \
             kv + (((size_t)(b * CC + c_)) * SS + (2 * (p_) + smp_)) * DD    \
                + pxg + sg_ * 4);                                            \
    } } while (0)

// load one pair's kv into registers (interleaved channels c = cg+16k)
#define KREG_LOAD(par_, slot_) do {                                          \
    const float* cu0_ = sm + SM_KV + (slot_) * 2048;                         \
    const float* cu1_ = cu0_ + 2048;                                         \
    _Pragma("unroll")                                                        \
    for (int u_ = 0; u_ < 4; ++u_) {                                         \
        kva[par_][u_] = pack2(cu0_[(cg + 32 * u_) * 16 + px],                \
                              cu0_[(cg + 32 * u_ + 16) * 16 + px]);          \
        kvb[par_][u_] = pack2(cu1_[(cg + 32 * u_) * 16 + px],                \
                              cu1_[(cg + 32 * u_ + 16) * 16 + px]);          \
    } } while (0)

__global__ void __launch_bounds__(NT, 1)
deform_attn_kernel(const float* __restrict__ q,
                   const float* __restrict__ kv,
                   const float* __restrict__ bq,
                   const float* __restrict__ bk,   // unused (softmax shift-inv)
                   const float* __restrict__ bv,
                   float* __restrict__ out) {
    extern __shared__ float sm[];

    const int t   = threadIdx.x;       // 256
    const int px  = t & 15;
    const int cg  = t >> 4;            // 0..15
    const int smp = t >> 7;            // reducer: sample-of-pair
    const int rh  = (t >> 4) & 7;      // reducer: head
    const int rp  = t & 15;            // reducer: pixel
    const int b   = blockIdx.y;
    const int pxg = blockIdx.x * TPX;

    float* attn0 = out + (size_t)BB * OCH * DD;
    float* attn1 = attn0 + (size_t)BB * NHD * 9 * DD;

    // ---- G0: WqT, WkT, q tile (into kv slots 4,5) ---------------------------
#pragma unroll
    for (int k = 0; k < 16; ++k) { int i = t + k * 256; cp16(sm + SM_WA + i * 4, g_WT + i * 4); }
#pragma unroll
    for (int k = 0; k < 16; ++k) { int i = t + k * 256; cp16(sm + SM_WK + i * 4, g_WT + 16384 + i * 4); }
#pragma unroll
    for (int k = 0; k < 2; ++k) {
        int i = t + k * 256; int c = i >> 2, sg = i & 3;
        cp16(sm + SM_KV + 4 * 2048 + c * 16 + sg * 4,
             q + ((size_t)(b * CC + c)) * DD + pxg + sg * 4);
    }
    CP_COMMIT();                       // G0
    LOAD_PAIR(0, 0); CP_COMMIT();      // G1
    LOAD_PAIR(1, 2); CP_COMMIT();      // G2
    CP_WAIT(2);                        // G0 done
    __syncthreads();

    // ---- P1: qp = Wq.x + bq -> [px][130] ------------------------------------
    {
        const int oc0 = cg * 8;
        ull a0 = pack2(bq[oc0],     bq[oc0 + 1]);
        ull a1 = pack2(bq[oc0 + 2], bq[oc0 + 3]);
        ull a2 = pack2(bq[oc0 + 4], bq[oc0 + 5]);
        ull a3 = pack2(bq[oc0 + 6], bq[oc0 + 7]);
        const float* qt_ = sm + SM_KV + 4 * 2048;
#pragma unroll 4
        for (int c = 0; c < CC; ++c) {
            float qv = qt_[c * 16 + px];
            ull q2 = pack2(qv, qv);
            const ulonglong2* w =
                reinterpret_cast<const ulonglong2*>(sm + SM_WA + c * OCH + oc0);
            ulonglong2 w0 = w[0], w1 = w[1];
            a0 = fma2(w0.x, q2, a0); a1 = fma2(w0.y, q2, a1);
            a2 = fma2(w1.x, q2, a2); a3 = fma2(w1.y, q2, a3);
        }
        float2* qp = reinterpret_cast<float2*>(sm + SM_QP + px * 130 + oc0);
        qp[0] = unpack2(a0); qp[1] = unpack2(a1);
        qp[2] = unpack2(a2); qp[3] = unpack2(a3);
    }
    __syncthreads();

    // G3: WvT -> SM_WA
#pragma unroll
    for (int k = 0; k < 16; ++k) { int i = t + k * 256; cp16(sm + SM_WA + i * 4, g_WT + 32768 + i * 4); }
    CP_COMMIT();

    // ---- P2: qtilde, interleaved channels (cg+32u, cg+32u+16) ---------------
    ull qt2[NHD][4];
#pragma unroll
    for (int h = 0; h < NHD; ++h) {
        const ull* qpp = reinterpret_cast<const ull*>(sm + SM_QP + px * 130 + h * 16);
        ull qp2[8];
#pragma unroll
        for (int j = 0; j < 8; ++j) qp2[j] = qpp[j];
#pragma unroll
        for (int u = 0; u < 4; ++u) {
            const int cx = cg + 32 * u, cy = cx + 16;
            const ulonglong2* wx =
                reinterpret_cast<const ulonglong2*>(sm + SM_WK + cx * OCH + h * 16);
            const ulonglong2* wy =
                reinterpret_cast<const ulonglong2*>(sm + SM_WK + cy * OCH + h * 16);
            ull ax = 0ull, ay = 0ull;
#pragma unroll
            for (int j = 0; j < 4; ++j) {
                ulonglong2 wxx = wx[j];
                ax = fma2(wxx.x, qp2[2 * j], ax);
                ax = fma2(wxx.y, qp2[2 * j + 1], ax);
                ulonglong2 wyy = wy[j];
                ay = fma2(wyy.x, qp2[2 * j], ay);
                ay = fma2(wyy.y, qp2[2 * j + 1], ay);
            }
            float2 vx = unpack2(ax), vy = unpack2(ay);
            qt2[h][u] = pack2(vx.x + vx.y, vy.x + vy.y);
        }
    }
    CP_WAIT(2);        // G1 (pair0) done
    __syncthreads();

    // ---- pipelined pair loop: 1 BAR per pair ---------------------------------
    ull kva[2][4], kvb[2][4];
    KREG_LOAD(0, 0);   // pair 0

    ull agg2[NHD][4];
#pragma unroll
    for (int h = 0; h < NHD; ++h)
#pragma unroll
        for (int u = 0; u < 4; ++u) agg2[h][u] = 0ull;

    float z0acc = 0.f, z1acc = 0.f;

#pragma unroll
    for (int i = 0; i < NP; ++i) {
        const int par = i & 1;

        // partials(i) -> pbuf[par]
        float* pb = sm + SM_PART + par * 4352;
#pragma unroll
        for (int h = 0; h < NHD; ++h) {
            ull a = 0ull, bb = 0ull;
#pragma unroll
            for (int u = 0; u < 4; ++u) {
                a  = fma2(qt2[h][u], kva[par][u], a);
                bb = fma2(qt2[h][u], kvb[par][u], bb);
            }
            float2 va = unpack2(a), vb = unpack2(bb);
            pb[h * 272 + cg * 16 + px]        = va.x + va.y;
            pb[2176 + h * 272 + cg * 16 + px] = vb.x + vb.y;
        }

        if (i + 2 < NP) { LOAD_PAIR(i + 2, ((i + 2) % 3) * 2); CP_COMMIT(); }
        if (i == 0)          { CP_WAIT(2); }
        else if (i + 2 < NP) { CP_WAIT(1); }
        else                 { CP_WAIT(0); }
        __syncthreads();   // BAR(i)

        // reduce(i): all 256 threads, one (smp, h, px) each
        {
            const float* pp = sm + SM_PART + par * 4352 + smp * 2176 + rh * 272 + rp;
            float sum = 0.f;
#pragma unroll
            for (int j = 0; j < 16; ++j) sum += pp[j * 16];
            float w = __expf(sum * SCALE_F);
            const int s = 2 * i + smp;
            sm[SM_LOGW + rh * 304 + s * 16 + rp] = w;
            if (s < 9) z0acc += w; else z1acc += w;
        }

        // agg(i-1): w(i-1) ordered by BAR(i)
        if (i > 0) {
            const int pj = (i - 1) & 1, sA = 2 * (i - 1);
#pragma unroll
            for (int h = 0; h < NHD; ++h) {
                float wa = sm[SM_LOGW + h * 304 + sA * 16 + px];
                float wb = sm[SM_LOGW + h * 304 + (sA + 1) * 16 + px];
                ull wa2 = pack2(wa, wa), wb2 = pack2(wb, wb);
#pragma unroll
                for (int u = 0; u < 4; ++u) {
                    agg2[h][u] = fma2(kva[pj][u], wa2, agg2[h][u]);
                    agg2[h][u] = fma2(kvb[pj][u], wb2, agg2[h][u]);
                }
            }
        }

        // load kreg(i+1)
        if (i < NP - 1) {
            const int np_ = (i + 1) & 1;
            KREG_LOAD(np_, ((i + 1) % 3) * 2);
        }
    }
    __syncthreads();   // w(8) visible

    // ---- agg(8) --------------------------------------------------------------
    {
        const int sA = 16;
#pragma unroll
        for (int h = 0; h < NHD; ++h) {
            float wa = sm[SM_LOGW + h * 304 + sA * 16 + px];
            float wb = sm[SM_LOGW + h * 304 + (sA + 1) * 16 + px];
            ull wa2 = pack2(wa, wa), wb2 = pack2(wb, wb);
#pragma unroll
            for (int u = 0; u < 4; ++u) {
                agg2[h][u] = fma2(kva[0][u], wa2, agg2[h][u]);
                agg2[h][u] = fma2(kvb[0][u], wb2, agg2[h][u]);
            }
        }
    }

    // ---- stage agg (interleaved c positions) + z parts -----------------------
#pragma unroll
    for (int h = 0; h < NHD; ++h)
#pragma unroll
        for (int u = 0; u < 4; ++u) {
            float2 v = unpack2(agg2[h][u]);
            sm[SM_AGG + h * 2080 + px * 130 + cg + 32 * u]      = v.x;
            sm[SM_AGG + h * 2080 + px * 130 + cg + 32 * u + 16] = v.y;
        }
    sm[SM_Z + t]       = z0acc;
    sm[SM_Z + 256 + t] = z1acc;
    __syncthreads();

    float Z0 = 0.f, Z1 = 0.f;
    if (t < 128) {
        Z0 = sm[SM_Z + t] + sm[SM_Z + t + 128];
        Z1 = sm[SM_Z + 256 + t] + sm[SM_Z + 256 + t + 128];
        sm[SM_IZ + t] = 1.f / (Z0 + Z1);
    }
    __syncthreads();

    // ---- P5: out[oc][px] = (WvT . agg_h) * invZ + bv --------------------------
    {
        const int oc0 = cg * 8;
        const int h5  = cg >> 1;
        const float* ag = sm + SM_AGG + h5 * 2080 + px * 130;
        ull a0 = 0ull, a1 = 0ull, a2 = 0ull, a3 = 0ull;
#pragma unroll 4
        for (int c = 0; c < CC; c += 2) {
            float2 av = *reinterpret_cast<const float2*>(ag + c);
            ull p0 = pack2(av.x, av.x);
            ull p1 = pack2(av.y, av.y);
            const ulonglong2* w0 =
                reinterpret_cast<const ulonglong2*>(sm + SM_WA + c * OCH + oc0);
            const ulonglong2* w1 =
                reinterpret_cast<const ulonglong2*>(sm + SM_WA + (c + 1) * OCH + oc0);
            ulonglong2 wA = w0[0], wB = w0[1], wC = w1[0], wD = w1[1];
            a0 = fma2(wA.x, p0, a0); a1 = fma2(wA.y, p0, a1);
            a2 = fma2(wB.x, p0, a2); a3 = fma2(wB.y, p0, a3);
            a0 = fma2(wC.x, p1, a0); a1 = fma2(wC.y, p1, a1);
            a2 = fma2(wD.x, p1, a2); a3 = fma2(wD.y, p1, a3);
        }
        float iz = sm[SM_IZ + h5 * 16 + px];
        float2 v0 = unpack2(a0), v1 = unpack2(a1);
        float2 v2 = unpack2(a2), v3 = unpack2(a3);
        size_t base = ((size_t)(b * OCH + oc0)) * DD + pxg + px;
        out[base]          = v0.x * iz + bv[oc0];
        out[base + DD]     = v0.y * iz + bv[oc0 + 1];
        out[base + 2 * DD] = v1.x * iz + bv[oc0 + 2];
        out[base + 3 * DD] = v1.y * iz + bv[oc0 + 3];
        out[base + 4 * DD] = v2.x * iz + bv[oc0 + 4];
        out[base + 5 * DD] = v2.y * iz + bv[oc0 + 5];
        out[base + 6 * DD] = v3.x * iz + bv[oc0 + 6];
        out[base + 7 * DD] = v3.y * iz + bv[oc0 + 7];
    }

    // ---- epilogue: half softmaxes --------------------------------------------
    if (t < 128) {
        float iz0 = 1.f / Z0, iz1 = 1.f / Z1;
        size_t base = ((size_t)(b * NHD + rh) * 9) * DD + pxg + rp;
#pragma unroll
        for (int s = 0; s < 9; ++s) {
            attn0[base + (size_t)s * DD] =
                sm[SM_LOGW + rh * 304 + s * 16 + rp] * iz0;
            attn1[base + (size_t)s * DD] =
                sm[SM_LOGW + rh * 304 + (s + 9) * 16 + rp] * iz1;
        }
    }
}

// ---------------------------------------------------------------------------
extern "C" void kernel_launch(void* const* d_in, const int* in_sizes, int n_in,
                              void* d_out, int out_size) {
    const float* q  = (const float*)d_in[0];
    const float* kv = (const float*)d_in[1];
    const float* Wq = (const float*)d_in[2];
    const float* bq = (const float*)d_in[3];
    const float* Wk = (const float*)d_in[4];
    const float* bk = (const float*)d_in[5];
    const float* Wv = (const float*)d_in[6];
    const float* bv = (const float*)d_in[7];
    float* out = (float*)d_out;

    cudaFuncSetAttribute(deform_attn_kernel,
                         cudaFuncAttributeMaxDynamicSharedMemorySize,
                         SM_TOTAL_F * 4);

    transpose_w_kernel<<<192, 256>>>(Wq, Wk, Wv);
    deform_attn_kernel<<<dim3(DD / TPX, BB), NT, SM_TOTAL_F * 4>>>(
        q, kv, bq, bk, bv, out);
}